// round 1
// baseline (speedup 1.0000x reference)
#include <cuda_runtime.h>

// DEER LIF fixed-point solver, restructured as a single wavefront sweep over t.
// y_k[t] = a_k[t] * y_k[t-1] + rhs_k[t], where a_k, rhs_k depend on x[t] and
// y_{k-1}[t-1]. All 10 iterations advance together; 11 state regs per chain.

#define T_LEN 1024
#define NE    16384      // B*F = 32*512
#define NITER 10
#define PF    4          // x prefetch depth (covers ~4*per-t compute > DRAM lat)

__global__ __launch_bounds__(64)
void deer_lif_kernel(const float* __restrict__ x,
                     const float* __restrict__ v_init,
                     float* __restrict__ out)
{
    const int e = blockIdx.x * blockDim.x + threadIdx.x;
    if (e >= NE) return;

    const float v0 = v_init[e];

    // p[k] = y^{(k)}[t-1]; all recurrences start from v_init, and the shift
    // _shift(y, v_init) also injects v_init at t=0.
    float p[NITER + 1];
#pragma unroll
    for (int k = 0; k <= NITER; ++k) p[k] = v0;

    float* __restrict__ spike_out = out;                       // (T,B,F)
    float* __restrict__ y_out     = out + (size_t)T_LEN * NE;  // (T,B,F)

    // software prefetch pipeline for x[t]
    float xb[PF];
#pragma unroll
    for (int i = 0; i < PF; ++i) xb[i] = x[(size_t)i * NE + e];

#pragma unroll 4
    for (int t = 0; t < T_LEN; ++t) {
        const float xt = xb[0];
#pragma unroll
        for (int i = 0; i < PF - 1; ++i) xb[i] = xb[i + 1];
        const int tp = t + PF;
        xb[PF - 1] = (tp < T_LEN) ? x[(size_t)tp * NE + e] : 0.0f;

        float c[NITER + 1];

        // Warmstart row y^{(0)}[t]: continuous dynamics for t<WARM(=2), else 0.
        // h = v + (x - v)/TAU with TAU=2.
        c[0] = (t < 2) ? fmaf(xt - p[0], 0.5f, p[0]) : 0.0f;

        // 10 Newton/fixed-point rows, all using state from t-1 only.
#pragma unroll
        for (int k = 1; k <= NITER; ++k) {
            const float ys = p[k - 1];
            const float h  = fmaf(xt - ys, 0.5f, ys);          // L[y], TAU=2
            const float hc = fminf(fmaxf(h, -20.0f), 20.0f);   // clip
            const float z  = 4.0f * (hc - 0.7f);               // ALPHA*(hc-VTH)
            const float ez = __expf(-z);
            const float s  = __fdividef(1.0f, 1.0f + ez);      // sigmoid
            const float sg = 4.0f * s * (1.0f - s);            // surrogate grad
            const float a  = 0.5f * (1.0f - sg);               // a = -G = decay*(1-sg)
            const float rhs = fmaf(-a, ys, h);                 // h + G*ys
            c[k] = fmaf(a, p[k], rhs);                         // y_k[t]
        }

#pragma unroll
        for (int k = 0; k <= NITER; ++k) p[k] = c[k];

        const float yv = c[NITER];
        const size_t o = (size_t)t * NE + e;
        y_out[o]     = yv;
        spike_out[o] = (yv >= 0.7f) ? 1.0f : 0.0f;
    }
}

extern "C" void kernel_launch(void* const* d_in, const int* in_sizes, int n_in,
                              void* d_out, int out_size)
{
    const float* x      = (const float*)d_in[0];   // (T,B,F) float32
    const float* v_init = (const float*)d_in[1];   // (B,F)   float32
    float* out          = (float*)d_out;           // [spike; y] concat

    const int block = 64;
    const int grid  = NE / block;                  // 256 blocks
    deer_lif_kernel<<<grid, block>>>(x, v_init, out);
}

// round 2
// speedup vs baseline: 2.9167x; 2.9167x over previous
#include <cuda_runtime.h>

// DEER LIF fixed-point solver as a wavefront sweep over t (all 10 iterations
// advance together, 11 state regs), time-split into 4 chunks with a 64-step
// contraction halo for occupancy.

#define T_LEN   1024
#define NE      16384      // B*F
#define NITER   10
#define CHUNK   256
#define HALO    64
#define NCHUNKS 4
#define PF      4
#define BLOCK   128

__device__ __forceinline__ float sigmoid4(float h) {
    // sigmoid(4*(h - 0.7)) = 1 / (1 + exp2((2.8 - 4h)*log2e))
    float ax = fmaf(h, -5.770780163555852f, 4.039546114489096f);
    float ez;
    asm("ex2.approx.ftz.f32 %0, %1;" : "=f"(ez) : "f"(ax));
    float s;
    asm("rcp.approx.ftz.f32 %0, %1;" : "=f"(s) : "f"(1.0f + ez));
    return s;
}

template <bool STORE>
__device__ __forceinline__ void lif_step(int t, float xt, float* __restrict__ p,
                                         float* __restrict__ spike_out,
                                         float* __restrict__ y_out, int e)
{
    const float hx = 0.5f * xt;
    // Descending k: row k reads old p[k-1], old p[k]; rows are independent.
#pragma unroll
    for (int k = NITER; k >= 1; --k) {
        const float ys = p[k - 1];
        const float h  = fmaf(0.5f, ys, hx);       // L[y], TAU=2
        const float s  = sigmoid4(h);
        const float q  = s * (1.0f - s);           // sg/4
        const float a  = fmaf(q, -2.0f, 0.5f);     // 0.5*(1-sg)
        p[k] = fmaf(a, p[k] - ys, h);              // a*y_prev + (h - a*ys)
    }
    // warmstart row: continuous dynamics for t<2, else exactly 0
    p[0] = (t < 2) ? fmaf(0.5f, p[0], hx) : 0.0f;

    if (STORE) {
        const float yv = p[NITER];
        const size_t o = (size_t)t * NE + e;
        y_out[o]     = yv;
        spike_out[o] = (yv >= 0.7f) ? 1.0f : 0.0f;
    }
}

__global__ __launch_bounds__(BLOCK, 4)
void deer_lif_kernel(const float* __restrict__ x,
                     const float* __restrict__ v_init,
                     float* __restrict__ out)
{
    const int e       = blockIdx.x * BLOCK + threadIdx.x;
    const int chunk   = blockIdx.y;
    const int t_write = chunk * CHUNK;
    const int t_begin = (chunk == 0) ? 0 : (t_write - HALO);
    const int t_end   = t_write + CHUNK;

    float p[NITER + 1];
    const float init = (chunk == 0) ? v_init[e] : 0.0f;
#pragma unroll
    for (int k = 0; k <= NITER; ++k) p[k] = init;

    float* __restrict__ spike_out = out;
    float* __restrict__ y_out     = out + (size_t)T_LEN * NE;

    const float* __restrict__ xp = x + e;

    // software prefetch pipeline for x[t]
    float xb[PF];
#pragma unroll
    for (int i = 0; i < PF; ++i)
        xb[i] = xp[(size_t)(t_begin + i) * NE];

    // halo warm-in: no stores (empty for chunk 0)
#pragma unroll 4
    for (int t = t_begin; t < t_write; ++t) {
        const float xt = xb[0];
#pragma unroll
        for (int i = 0; i < PF - 1; ++i) xb[i] = xb[i + 1];
        const int tp = t + PF;
        xb[PF - 1] = (tp < T_LEN) ? xp[(size_t)tp * NE] : 0.0f;
        lif_step<false>(t, xt, p, spike_out, y_out, e);
    }

    // main span: store spike + y
#pragma unroll 4
    for (int t = t_write; t < t_end; ++t) {
        const float xt = xb[0];
#pragma unroll
        for (int i = 0; i < PF - 1; ++i) xb[i] = xb[i + 1];
        const int tp = t + PF;
        xb[PF - 1] = (tp < T_LEN) ? xp[(size_t)tp * NE] : 0.0f;
        lif_step<true>(t, xt, p, spike_out, y_out, e);
    }
}

extern "C" void kernel_launch(void* const* d_in, const int* in_sizes, int n_in,
                              void* d_out, int out_size)
{
    const float* x      = (const float*)d_in[0];   // (T,B,F) float32
    const float* v_init = (const float*)d_in[1];   // (B,F)   float32
    float* out          = (float*)d_out;           // [spike; y]

    dim3 grid(NE / BLOCK, NCHUNKS);
    deer_lif_kernel<<<grid, BLOCK>>>(x, v_init, out);
}

// round 3
// speedup vs baseline: 3.3325x; 1.1426x over previous
#include <cuda_runtime.h>

// DEER LIF wavefront solver, 4 time-chunks (halo 64) x 2-lane split of the 10
// iteration rows. Lanes 0-15 of a warp run rows 1-5, lanes 16-31 run rows 6-10
// of the same 16 elements; row 6's input y5[t-1] crosses via one shfl per step.

#define T_LEN   1024
#define NE      16384
#define CHUNK   256
#define HALO    64
#define NCHUNKS 4
#define PF      4
#define BLOCK   128
#define RPT     5        // rows per thread

// ax = (2.8 - 4h)*log2(e)
#define C_NEG (-5.770780163555852f)
#define C_POS ( 4.039546114489096f)

__device__ __forceinline__ float row_update(float pk, float ys, float hx) {
    const float h  = fmaf(0.5f, ys, hx);
    const float ax = fmaf(h, C_NEG, C_POS);
    float ez, s;
    asm("ex2.approx.ftz.f32 %0, %1;" : "=f"(ez) : "f"(ax));
    asm("rcp.approx.ftz.f32 %0, %1;" : "=f"(s) : "f"(1.0f + ez));
    const float qq = fmaf(-s, s, s);          // s*(1-s)
    const float a  = fmaf(qq, -2.0f, 0.5f);   // 0.5*(1-sg)
    return fmaf(a, pk - ys, h);               // a*y_prev + (h - a*ys)
}

template <bool STORE>
__device__ __forceinline__ void lif_step(int t, float xt,
                                         float* __restrict__ q, float& p0,
                                         bool upper,
                                         float* __restrict__ spike_out,
                                         float* __restrict__ y_out, int e)
{
    // p5[t-1] from the lower half (upper half's payload is ignored by lower)
    const float y5x = __shfl_xor_sync(0xffffffffu, q[RPT - 1], 16);
    const float ys0 = upper ? y5x : p0;
    const float hx  = 0.5f * xt;

    // descending so q[j] reads old q[j-1]
#pragma unroll
    for (int j = RPT - 1; j >= 1; --j)
        q[j] = row_update(q[j], q[j - 1], hx);
    q[0] = row_update(q[0], ys0, hx);

    // warmstart row (nonzero only for t<2; uniform across warp)
    p0 = (t < 2) ? fmaf(0.5f, p0, hx) : 0.0f;

    if (STORE && upper) {
        const float yv = q[RPT - 1];              // y_10
        const size_t o = (size_t)t * NE + e;
        y_out[o]     = yv;
        spike_out[o] = (yv >= 0.7f) ? 1.0f : 0.0f;
    }
}

__global__ __launch_bounds__(BLOCK, 7)
void deer_lif_kernel(const float* __restrict__ x,
                     const float* __restrict__ v_init,
                     float* __restrict__ out)
{
    const int lane  = threadIdx.x & 31;
    const int sub   = lane & 15;
    const bool upper = lane >= 16;
    const int warp  = threadIdx.x >> 5;
    const int e     = blockIdx.x * 64 + warp * 16 + sub;

    const int chunk   = blockIdx.y;
    const int t_write = chunk * CHUNK;
    const int t_begin = (chunk == 0) ? 0 : (t_write - HALO);
    const int t_end   = t_write + CHUNK;

    const float init = (chunk == 0) ? v_init[e] : 0.0f;
    float q[RPT];
#pragma unroll
    for (int j = 0; j < RPT; ++j) q[j] = init;
    float p0 = init;

    float* __restrict__ spike_out = out;
    float* __restrict__ y_out     = out + (size_t)T_LEN * NE;
    const float* __restrict__ xp  = x + e;

    float xb[PF];
#pragma unroll
    for (int i = 0; i < PF; ++i)
        xb[i] = xp[(size_t)(t_begin + i) * NE];

    // halo warm-in (empty for chunk 0)
#pragma unroll 4
    for (int t = t_begin; t < t_write; ++t) {
        const float xt = xb[0];
#pragma unroll
        for (int i = 0; i < PF - 1; ++i) xb[i] = xb[i + 1];
        const int tp = t + PF;
        xb[PF - 1] = (tp < T_LEN) ? xp[(size_t)tp * NE] : 0.0f;
        lif_step<false>(t, xt, q, p0, upper, spike_out, y_out, e);
    }

    // main span
#pragma unroll 4
    for (int t = t_write; t < t_end; ++t) {
        const float xt = xb[0];
#pragma unroll
        for (int i = 0; i < PF - 1; ++i) xb[i] = xb[i + 1];
        const int tp = t + PF;
        xb[PF - 1] = (tp < T_LEN) ? xp[(size_t)tp * NE] : 0.0f;
        lif_step<true>(t, xt, q, p0, upper, spike_out, y_out, e);
    }
}

extern "C" void kernel_launch(void* const* d_in, const int* in_sizes, int n_in,
                              void* d_out, int out_size)
{
    const float* x      = (const float*)d_in[0];   // (T,B,F) float32
    const float* v_init = (const float*)d_in[1];   // (B,F)   float32
    float* out          = (float*)d_out;           // [spike; y]

    dim3 grid(NE / 64, NCHUNKS);                   // (256, 4)
    deer_lif_kernel<<<grid, BLOCK>>>(x, v_init, out);
}

// round 4
// speedup vs baseline: 3.4426x; 1.0330x over previous
#include <cuda_runtime.h>

// DEER LIF wavefront solver: 4 balanced time-chunks (all blocks run 304 steps),
// 2-lane split of the 10 iteration rows (5 rows/thread), paired rcp (5 EX2 +
// 3 RCP per thread-step instead of 5+5).

#define T_LEN   1024
#define NE      16384
#define NCHUNKS 4
#define SPAN    304      // steps per block (halo+write, uniform)
#define STRIDE  240      // write span of chunks 1..3
#define HALO    64
#define PF      4
#define BLOCK   128
#define RPT     5

// ax = (2.8 - 4h)*log2(e)
#define C_NEG (-5.770780163555852f)
#define C_POS ( 4.039546114489096f)

__device__ __forceinline__ float ex2f(float a) {
    float r; asm("ex2.approx.ftz.f32 %0, %1;" : "=f"(r) : "f"(a)); return r;
}
__device__ __forceinline__ float rcpf(float a) {
    float r; asm("rcp.approx.ftz.f32 %0, %1;" : "=f"(r) : "f"(a)); return r;
}

template <bool STORE>
__device__ __forceinline__ void lif_step(int t, float xt,
                                         float* __restrict__ q, float& p0,
                                         bool upper,
                                         float* __restrict__ spike_out,
                                         float* __restrict__ y_out, int e)
{
    // y5[t-1] from the lower half-warp (payload ignored in the other direction)
    const float y5x = __shfl_xor_sync(0xffffffffu, q[RPT - 1], 16);
    const float hx  = 0.5f * xt;

    float ys[RPT];
    ys[0] = upper ? y5x : p0;
#pragma unroll
    for (int j = 1; j < RPT; ++j) ys[j] = q[j - 1];

    float h[RPT], w[RPT];
#pragma unroll
    for (int j = 0; j < RPT; ++j) {
        h[j] = fmaf(0.5f, ys[j], hx);
        w[j] = 1.0f + ex2f(fmaf(h[j], C_NEG, C_POS));
    }

    // paired reciprocals: 3 RCP for 5 sigmoids
    float s[RPT];
    const float r43 = rcpf(w[4] * w[3]);
    s[4] = r43 * w[3];
    s[3] = r43 * w[4];
    const float r21 = rcpf(w[2] * w[1]);
    s[2] = r21 * w[1];
    s[1] = r21 * w[2];
    s[0] = rcpf(w[0]);

#pragma unroll
    for (int j = 0; j < RPT; ++j) {
        const float qq = fmaf(-s[j], s[j], s[j]);   // s*(1-s)
        const float a  = fmaf(qq, -2.0f, 0.5f);     // 0.5*(1-sg)
        q[j] = fmaf(a, q[j] - ys[j], h[j]);         // a*y_prev + (h - a*ys)
    }

    // warmstart row (nonzero only for t<2; uniform across warp)
    p0 = (t < 2) ? fmaf(0.5f, p0, hx) : 0.0f;

    if (STORE && upper) {
        const float yv = q[RPT - 1];                // y_10
        const size_t o = (size_t)t * NE + e;
        y_out[o]     = yv;
        spike_out[o] = (yv >= 0.7f) ? 1.0f : 0.0f;
    }
}

__global__ __launch_bounds__(BLOCK, 7)
void deer_lif_kernel(const float* __restrict__ x,
                     const float* __restrict__ v_init,
                     float* __restrict__ out)
{
    const int lane   = threadIdx.x & 31;
    const int sub    = lane & 15;
    const bool upper = lane >= 16;
    const int warp   = threadIdx.x >> 5;
    const int e      = blockIdx.x * 64 + warp * 16 + sub;

    const int chunk   = blockIdx.y;
    const int t_begin = STRIDE * chunk;              // 0,240,480,720
    const int t_end   = t_begin + SPAN;              // 304,544,784,1024
    const int t_write = (chunk == 0) ? 0 : t_begin + HALO;

    const float init = (chunk == 0) ? v_init[e] : 0.0f;
    float q[RPT];
#pragma unroll
    for (int j = 0; j < RPT; ++j) q[j] = init;
    float p0 = init;

    float* __restrict__ spike_out = out;
    float* __restrict__ y_out     = out + (size_t)T_LEN * NE;
    const float* __restrict__ xp  = x + e;

    float xb[PF];
#pragma unroll
    for (int i = 0; i < PF; ++i)
        xb[i] = xp[(size_t)(t_begin + i) * NE];

    // halo warm-in (empty for chunk 0)
#pragma unroll 4
    for (int t = t_begin; t < t_write; ++t) {
        const float xt = xb[0];
#pragma unroll
        for (int i = 0; i < PF - 1; ++i) xb[i] = xb[i + 1];
        const int tp = t + PF;
        xb[PF - 1] = (tp < T_LEN) ? xp[(size_t)tp * NE] : 0.0f;
        lif_step<false>(t, xt, q, p0, upper, spike_out, y_out, e);
    }

    // main span
#pragma unroll 4
    for (int t = t_write; t < t_end; ++t) {
        const float xt = xb[0];
#pragma unroll
        for (int i = 0; i < PF - 1; ++i) xb[i] = xb[i + 1];
        const int tp = t + PF;
        xb[PF - 1] = (tp < T_LEN) ? xp[(size_t)tp * NE] : 0.0f;
        lif_step<true>(t, xt, q, p0, upper, spike_out, y_out, e);
    }
}

extern "C" void kernel_launch(void* const* d_in, const int* in_sizes, int n_in,
                              void* d_out, int out_size)
{
    const float* x      = (const float*)d_in[0];   // (T,B,F) float32
    const float* v_init = (const float*)d_in[1];   // (B,F)   float32
    float* out          = (float*)d_out;           // [spike; y]

    dim3 grid(NE / 64, NCHUNKS);                   // (256, 4)
    deer_lif_kernel<<<grid, BLOCK>>>(x, v_init, out);
}

// round 5
// speedup vs baseline: 3.4479x; 1.0015x over previous
#include <cuda_runtime.h>

// DEER LIF wavefront solver: 4 balanced time-chunks (all blocks run 304 steps),
// 2-lane split of the 10 iteration rows (5 rows/thread), paired rcp (5 EX2 +
// 3 RCP per thread-step instead of 5+5).

#define T_LEN   1024
#define NE      16384
#define NCHUNKS 4
#define SPAN    304      // steps per block (halo+write, uniform)
#define STRIDE  240      // write span of chunks 1..3
#define HALO    64
#define PF      4
#define BLOCK   128
#define RPT     5

// ax = (2.8 - 4h)*log2(e)
#define C_NEG (-5.770780163555852f)
#define C_POS ( 4.039546114489096f)

__device__ __forceinline__ float ex2f(float a) {
    float r; asm("ex2.approx.ftz.f32 %0, %1;" : "=f"(r) : "f"(a)); return r;
}
__device__ __forceinline__ float rcpf(float a) {
    float r; asm("rcp.approx.ftz.f32 %0, %1;" : "=f"(r) : "f"(a)); return r;
}

template <bool STORE>
__device__ __forceinline__ void lif_step(int t, float xt,
                                         float* __restrict__ q, float& p0,
                                         bool upper,
                                         float* __restrict__ spike_out,
                                         float* __restrict__ y_out, int e)
{
    // y5[t-1] from the lower half-warp (payload ignored in the other direction)
    const float y5x = __shfl_xor_sync(0xffffffffu, q[RPT - 1], 16);
    const float hx  = 0.5f * xt;

    float ys[RPT];
    ys[0] = upper ? y5x : p0;
#pragma unroll
    for (int j = 1; j < RPT; ++j) ys[j] = q[j - 1];

    float h[RPT], w[RPT];
#pragma unroll
    for (int j = 0; j < RPT; ++j) {
        h[j] = fmaf(0.5f, ys[j], hx);
        w[j] = 1.0f + ex2f(fmaf(h[j], C_NEG, C_POS));
    }

    // paired reciprocals: 3 RCP for 5 sigmoids
    float s[RPT];
    const float r43 = rcpf(w[4] * w[3]);
    s[4] = r43 * w[3];
    s[3] = r43 * w[4];
    const float r21 = rcpf(w[2] * w[1]);
    s[2] = r21 * w[1];
    s[1] = r21 * w[2];
    s[0] = rcpf(w[0]);

#pragma unroll
    for (int j = 0; j < RPT; ++j) {
        const float qq = fmaf(-s[j], s[j], s[j]);   // s*(1-s)
        const float a  = fmaf(qq, -2.0f, 0.5f);     // 0.5*(1-sg)
        q[j] = fmaf(a, q[j] - ys[j], h[j]);         // a*y_prev + (h - a*ys)
    }

    // warmstart row (nonzero only for t<2; uniform across warp)
    p0 = (t < 2) ? fmaf(0.5f, p0, hx) : 0.0f;

    if (STORE && upper) {
        const float yv = q[RPT - 1];                // y_10
        const size_t o = (size_t)t * NE + e;
        y_out[o]     = yv;
        spike_out[o] = (yv >= 0.7f) ? 1.0f : 0.0f;
    }
}

__global__ __launch_bounds__(BLOCK, 7)
void deer_lif_kernel(const float* __restrict__ x,
                     const float* __restrict__ v_init,
                     float* __restrict__ out)
{
    const int lane   = threadIdx.x & 31;
    const int sub    = lane & 15;
    const bool upper = lane >= 16;
    const int warp   = threadIdx.x >> 5;
    const int e      = blockIdx.x * 64 + warp * 16 + sub;

    const int chunk   = blockIdx.y;
    const int t_begin = STRIDE * chunk;              // 0,240,480,720
    const int t_end   = t_begin + SPAN;              // 304,544,784,1024
    const int t_write = (chunk == 0) ? 0 : t_begin + HALO;

    const float init = (chunk == 0) ? v_init[e] : 0.0f;
    float q[RPT];
#pragma unroll
    for (int j = 0; j < RPT; ++j) q[j] = init;
    float p0 = init;

    float* __restrict__ spike_out = out;
    float* __restrict__ y_out     = out + (size_t)T_LEN * NE;
    const float* __restrict__ xp  = x + e;

    float xb[PF];
#pragma unroll
    for (int i = 0; i < PF; ++i)
        xb[i] = xp[(size_t)(t_begin + i) * NE];

    // halo warm-in (empty for chunk 0)
#pragma unroll 4
    for (int t = t_begin; t < t_write; ++t) {
        const float xt = xb[0];
#pragma unroll
        for (int i = 0; i < PF - 1; ++i) xb[i] = xb[i + 1];
        const int tp = t + PF;
        xb[PF - 1] = (tp < T_LEN) ? xp[(size_t)tp * NE] : 0.0f;
        lif_step<false>(t, xt, q, p0, upper, spike_out, y_out, e);
    }

    // main span
#pragma unroll 4
    for (int t = t_write; t < t_end; ++t) {
        const float xt = xb[0];
#pragma unroll
        for (int i = 0; i < PF - 1; ++i) xb[i] = xb[i + 1];
        const int tp = t + PF;
        xb[PF - 1] = (tp < T_LEN) ? xp[(size_t)tp * NE] : 0.0f;
        lif_step<true>(t, xt, q, p0, upper, spike_out, y_out, e);
    }
}

extern "C" void kernel_launch(void* const* d_in, const int* in_sizes, int n_in,
                              void* d_out, int out_size)
{
    const float* x      = (const float*)d_in[0];   // (T,B,F) float32
    const float* v_init = (const float*)d_in[1];   // (B,F)   float32
    float* out          = (float*)d_out;           // [spike; y]

    dim3 grid(NE / 64, NCHUNKS);                   // (256, 4)
    deer_lif_kernel<<<grid, BLOCK>>>(x, v_init, out);
}